// round 16
// baseline (speedup 1.0000x reference)
#include <cuda_runtime.h>
#include <cuda_fp16.h>
#include <math.h>
#include <stdint.h>

#define D_MODEL 512
#define NHEAD 4
#define HEAD_DIM 128
#define NB 2
#define SEQ 4096
#define MTOT (NB * SEQ)
#define NT (SEQ / 128)

// fp16 scratch (allocation-free rule: device globals)
__device__ __half g_Q[NB * NHEAD * SEQ * HEAD_DIM];   // pre-scaled by scale*log2e
__device__ __half g_K[NB * NHEAD * SEQ * HEAD_DIM];
__device__ __half g_V[NB * NHEAD * SEQ * HEAD_DIM];
__device__ __half g_attn[MTOT * D_MODEL];
// fp16 copies of inputs (converted once per call)
__device__ __half g_hq[MTOT * D_MODEL];
__device__ __half g_hk[MTOT * D_MODEL];
__device__ __half g_hv[MTOT * D_MODEL];
__device__ __half g_hWq[D_MODEL * D_MODEL];
__device__ __half g_hWk[D_MODEL * D_MODEL];
__device__ __half g_hWv[D_MODEL * D_MODEL];
__device__ __half g_hWo[D_MODEL * D_MODEL];

#define Q_PRESCALE 0.1275174735772633f   // (1/sqrt(128)) * log2(e)

// ---------------------------------------------------------------------------
// helpers
// ---------------------------------------------------------------------------
__device__ __forceinline__ uint32_t smem_u32(const void* p) {
    return (uint32_t)__cvta_generic_to_shared(p);
}
__device__ __forceinline__ void ldsm_x4(uint32_t& r0, uint32_t& r1, uint32_t& r2,
                                        uint32_t& r3, uint32_t addr) {
    asm volatile("ldmatrix.sync.aligned.m8n8.x4.shared.b16 {%0,%1,%2,%3}, [%4];"
                 : "=r"(r0), "=r"(r1), "=r"(r2), "=r"(r3) : "r"(addr));
}
__device__ __forceinline__ void ldsm_x4_t(uint32_t& r0, uint32_t& r1, uint32_t& r2,
                                          uint32_t& r3, uint32_t addr) {
    asm volatile("ldmatrix.sync.aligned.m8n8.x4.trans.shared.b16 {%0,%1,%2,%3}, [%4];"
                 : "=r"(r0), "=r"(r1), "=r"(r2), "=r"(r3) : "r"(addr));
}
__device__ __forceinline__ void mma16(float* d, const uint32_t* a, uint32_t b0,
                                      uint32_t b1) {
    asm volatile(
        "mma.sync.aligned.m16n8k16.row.col.f32.f16.f16.f32 "
        "{%0,%1,%2,%3}, {%4,%5,%6,%7}, {%8,%9}, {%0,%1,%2,%3};\n"
        : "+f"(d[0]), "+f"(d[1]), "+f"(d[2]), "+f"(d[3])
        : "r"(a[0]), "r"(a[1]), "r"(a[2]), "r"(a[3]), "r"(b0), "r"(b1));
}
__device__ __forceinline__ void cp16(uint32_t dst, const void* src) {
    asm volatile("cp.async.cg.shared.global [%0], [%1], 16;" :: "r"(dst), "l"(src));
}
__device__ __forceinline__ void cp_commit() {
    asm volatile("cp.async.commit_group;");
}
__device__ __forceinline__ void cp_wait1() {
    asm volatile("cp.async.wait_group 1;");
}
__device__ __forceinline__ void cp_wait0() {
    asm volatile("cp.async.wait_group 0;");
}
__device__ __forceinline__ uint32_t h2u(__half2 v) { return *(uint32_t*)&v; }
__device__ __forceinline__ float ex2f(float x) {
    float r;
    asm("ex2.approx.f32 %0, %1;" : "=f"(r) : "f"(x));
    return r;
}

// ---------------------------------------------------------------------------
// fp32 -> fp16 conversion of inputs (once per call)
// ---------------------------------------------------------------------------
__global__ __launch_bounds__(256) void conv_h(
    const float* __restrict__ q, const float* __restrict__ k,
    const float* __restrict__ v, const float* __restrict__ wq,
    const float* __restrict__ wk, const float* __restrict__ wv,
    const float* __restrict__ wo) {
    const int z = blockIdx.y;
    const float* src;
    __half* dst;
    int n;
    switch (z) {
        case 0: src = q;  dst = g_hq;  n = MTOT * D_MODEL; break;
        case 1: src = k;  dst = g_hk;  n = MTOT * D_MODEL; break;
        case 2: src = v;  dst = g_hv;  n = MTOT * D_MODEL; break;
        case 3: src = wq; dst = g_hWq; n = D_MODEL * D_MODEL; break;
        case 4: src = wk; dst = g_hWk; n = D_MODEL * D_MODEL; break;
        case 5: src = wv; dst = g_hWv; n = D_MODEL * D_MODEL; break;
        default: src = wo; dst = g_hWo; n = D_MODEL * D_MODEL; break;
    }
    int i = (blockIdx.x * 256 + threadIdx.x) * 4;
    if (i >= n) return;
    float4 f = *(const float4*)&src[i];
    *(uint2*)&dst[i] = make_uint2(h2u(__floats2half2_rn(f.x, f.y)),
                                  h2u(__floats2half2_rn(f.z, f.w)));
}

// ---------------------------------------------------------------------------
// fp16 GEMM, cp.async double-buffered. CTA 128x128, BK=64, 8 warps (2x4).
//   mode 0: A=g_hq,  B=g_hWq -> g_Q (scaled)
//   mode 1: A=g_hk,  B=g_hWk -> g_K
//   mode 2: A=g_hWv, B=g_hv  -> g_V [B,H,S,128]
//   mode 3: A=g_attn, B=g_hWo -> fp32 Cout
// ---------------------------------------------------------------------------
#define GST 72
#define G_STAGE (128 * GST)

__global__ __launch_bounds__(256) void gemm_h(
    const float* __restrict__ bq, const float* __restrict__ bk,
    const float* __restrict__ bv, const float* __restrict__ bo,
    float* __restrict__ Cout, int base_mode) {
    extern __shared__ __align__(16) __half gsm[];

    const int mode = (base_mode == 3) ? 3 : (int)blockIdx.z;
    const __half* A = (mode == 0) ? g_hq : (mode == 1) ? g_hk
                     : (mode == 2) ? g_hWv : g_attn;
    const __half* Bm = (mode == 0) ? g_hWq : (mode == 1) ? g_hWk
                      : (mode == 2) ? g_hv : g_hWo;
    const float* bias = (mode == 0) ? bq : (mode == 1) ? bk
                       : (mode == 2) ? bv : bo;

    const int tid = threadIdx.x;
    const int lane = tid & 31, warp = tid >> 5;
    const int group = lane >> 2, tig = lane & 3;
    const int wm = warp >> 2, wn = warp & 3;
    const int m0 = (mode == 2) ? blockIdx.x * 128 : blockIdx.y * 128;
    const int n0 = (mode == 2) ? blockIdx.y * 128 : blockIdx.x * 128;

    const uint32_t smb = smem_u32(gsm);

    float acc[4][4][4];
#pragma unroll
    for (int i = 0; i < 4; i++)
#pragma unroll
        for (int j = 0; j < 4; j++)
#pragma unroll
            for (int q = 0; q < 4; q++) acc[i][j][q] = 0.f;

    auto issue_stage = [&](int it) {
        const uint32_t ab = smb + (uint32_t)((it & 1) * 2 * G_STAGE * 2);
        const uint32_t bb = ab + (uint32_t)(G_STAGE * 2);
        int k0 = it * 64;
#pragma unroll
        for (int t = 0; t < 4; t++) {
            int idx = tid + t * 256;
            int r = idx >> 3, c = (idx & 7) * 8;
            uint32_t doff = (uint32_t)((r * GST + c) * 2);
            cp16(ab + doff, A + (size_t)(m0 + r) * D_MODEL + k0 + c);
            cp16(bb + doff, Bm + (size_t)(n0 + r) * D_MODEL + k0 + c);
        }
    };

    issue_stage(0);
    cp_commit();

#pragma unroll 1
    for (int it = 0; it < 8; it++) {
        if (it < 7) {
            issue_stage(it + 1);
            cp_commit();
            cp_wait1();
        } else {
            cp_wait0();
        }
        __syncthreads();

        const uint32_t ab = smb + (uint32_t)((it & 1) * 2 * G_STAGE * 2);
        const uint32_t bb = ab + (uint32_t)(G_STAGE * 2);

#pragma unroll
        for (int ks = 0; ks < 4; ks++) {
            int kc = ks * 16;
            uint32_t a[4][4];
#pragma unroll
            for (int i = 0; i < 4; i++) {
                uint32_t ad = ab + (uint32_t)(((wm * 64 + i * 16 + (lane & 15)) * GST +
                                               kc + 8 * (lane >> 4)) * 2);
                ldsm_x4(a[i][0], a[i][1], a[i][2], a[i][3], ad);
            }
#pragma unroll
            for (int jb = 0; jb < 2; jb++) {
                int nb = wn * 32 + jb * 16;
                uint32_t b0, b1, b2, b3;
                uint32_t ad = bb + (uint32_t)(((nb + (lane & 7) + 8 * (lane >> 4)) * GST +
                                               kc + 8 * ((lane >> 3) & 1)) * 2);
                ldsm_x4(b0, b1, b2, b3, ad);
#pragma unroll
                for (int i = 0; i < 4; i++) {
                    mma16(acc[i][2 * jb], a[i], b0, b1);
                    mma16(acc[i][2 * jb + 1], a[i], b2, b3);
                }
            }
        }
        __syncthreads();
    }

#pragma unroll
    for (int i = 0; i < 4; i++) {
        int r = m0 + wm * 64 + i * 16 + group;
#pragma unroll
        for (int j = 0; j < 4; j++) {
            int c = n0 + wn * 32 + j * 8 + 2 * tig;
            if (mode == 2) {
                float v00 = acc[i][j][0] + bias[r];
                float v01 = acc[i][j][1] + bias[r];
                float v10 = acc[i][j][2] + bias[r + 8];
                float v11 = acc[i][j][3] + bias[r + 8];
                int hh = r >> 7, d = r & 127;
                int bt = c >> 12, s = c & (SEQ - 1);
                size_t p0 = (((size_t)(bt * NHEAD + hh) * SEQ) + s) * HEAD_DIM + d;
                g_V[p0] = __float2half_rn(v00);
                g_V[p0 + HEAD_DIM] = __float2half_rn(v01);
                g_V[p0 + 8] = __float2half_rn(v10);
                g_V[p0 + HEAD_DIM + 8] = __float2half_rn(v11);
            } else if (mode == 3) {
                Cout[(size_t)r * D_MODEL + c] = acc[i][j][0] + bias[c];
                Cout[(size_t)r * D_MODEL + c + 1] = acc[i][j][1] + bias[c + 1];
                Cout[(size_t)(r + 8) * D_MODEL + c] = acc[i][j][2] + bias[c];
                Cout[(size_t)(r + 8) * D_MODEL + c + 1] = acc[i][j][3] + bias[c + 1];
            } else {
                const float sc = (mode == 0) ? Q_PRESCALE : 1.0f;
                float v00 = acc[i][j][0] + bias[c];
                float v01 = acc[i][j][1] + bias[c + 1];
                float v10 = acc[i][j][2] + bias[c];
                float v11 = acc[i][j][3] + bias[c + 1];
                __half* C = (mode == 0) ? g_Q : g_K;
                int hh = c >> 7, d = c & 127;
                int b0i = r >> 12, s0 = r & (SEQ - 1);
                int b1i = (r + 8) >> 12, s1 = (r + 8) & (SEQ - 1);
                size_t p0 = (((size_t)(b0i * NHEAD + hh) * SEQ) + s0) * HEAD_DIM + d;
                size_t p1 = (((size_t)(b1i * NHEAD + hh) * SEQ) + s1) * HEAD_DIM + d;
                *(__half2*)&C[p0] = __floats2half2_rn(v00 * sc, v01 * sc);
                *(__half2*)&C[p1] = __floats2half2_rn(v10 * sc, v11 * sc);
            }
        }
    }
}

// ---------------------------------------------------------------------------
// Flash attention: Q tile 256 rows (warp owns 32 rows = 2 m-blocks), so every
// K/V B-fragment ldsm feeds 4 MMAs (was 2) -> 25% less LDS per tensor op.
// Grid (SEQ/256, B*H) = 128 CTAs = one full wave. KV tile 128 double-buffered.
// Quarter-split softmax. Q persistent in smem; qf reloaded per use.
// smem: Q 256*FST + 4 * 128*FST halves = 208896 B.
// ---------------------------------------------------------------------------
#define FST 136
#define KV_H (128 * FST)
#define Q_OFF (4 * KV_H)                    // Q region start (halves)
#define FLASH_SMEM ((4 * KV_H + 256 * FST) * 2)   // 208896 B

__device__ __forceinline__ void issue_kv(const __half* gK, const __half* gV,
                                         uint32_t kbase, uint32_t vbase,
                                         int kt, int tid) {
#pragma unroll
    for (int t = 0; t < 8; t++) {
        int idx = tid + t * 256;
        int r = idx >> 4, c = (idx & 15) * 8;
        uint32_t doff = (uint32_t)((r * FST + c) * 2);
        size_t goff = (size_t)(kt * 128 + r) * HEAD_DIM + c;
        cp16(kbase + doff, gK + goff);
        cp16(vbase + doff, gV + goff);
    }
}

__global__ __launch_bounds__(256, 1) void flash_h() {
    extern __shared__ __align__(16) __half sh[];

    const int tid = threadIdx.x;
    const int lane = tid & 31, warp = tid >> 5;
    const int group = lane >> 2, tig = lane & 3;
    const int q0 = blockIdx.x * 256;
    const int bh = blockIdx.y;
    const int b = bh >> 2, h = bh & 3;

    const __half* gQ = g_Q + (size_t)(bh * SEQ + q0) * HEAD_DIM;
    const __half* gK = g_K + (size_t)bh * SEQ * HEAD_DIM;
    const __half* gV = g_V + (size_t)bh * SEQ * HEAD_DIM;

    uint32_t kb[2], vb[2];
    kb[0] = smem_u32(sh);
    vb[0] = smem_u32(sh + KV_H);
    kb[1] = smem_u32(sh + 2 * KV_H);
    vb[1] = smem_u32(sh + 3 * KV_H);
    const uint32_t qsb = smem_u32(sh + Q_OFF);

    // start KV tile 0 so it overlaps Q staging
    issue_kv(gK, gV, kb[0], vb[0], 0, tid);
    cp_commit();

    // stage Q (256 rows) into its persistent region
#pragma unroll
    for (int t = 0; t < 16; t++) {
        int idx = tid + t * 256;           // 4096 x 16B
        int r = idx >> 4, c = (idx & 15) * 8;
        *(uint4*)&sh[Q_OFF + r * FST + c] = *(const uint4*)&gQ[(size_t)r * HEAD_DIM + c];
    }

    float o[2][16][4];
#pragma unroll
    for (int i = 0; i < 2; i++)
#pragma unroll
        for (int j = 0; j < 16; j++)
#pragma unroll
            for (int q = 0; q < 4; q++) o[i][j][q] = 0.f;
    float l_lo[2] = {0.f, 0.f}, l_hi[2] = {0.f, 0.f};

    // qf addresses for the two m-blocks (rows 32w+16i)
    uint32_t qad[2];
#pragma unroll
    for (int i = 0; i < 2; i++)
        qad[i] = qsb + (uint32_t)(((32 * warp + 16 * i + (lane & 15)) * FST +
                                   8 * (lane >> 4)) * 2);

#pragma unroll 1
    for (int kt = 0; kt < NT; kt++) {
        if (kt + 1 < NT) {
            issue_kv(gK, gV, kb[(kt + 1) & 1], vb[(kt + 1) & 1], kt + 1, tid);
            cp_commit();
            cp_wait1();
        } else {
            cp_wait0();
        }
        __syncthreads();

        const uint32_t kbase = kb[kt & 1], vbase = vb[kt & 1];

        uint32_t pPrev[2][8];
#pragma unroll
        for (int q = 0; q < 4; q++) {
            // QK quarter q: S cols 32q..32q+31, both m-blocks
            float s[2][4][4];
#pragma unroll
            for (int i = 0; i < 2; i++)
#pragma unroll
                for (int j = 0; j < 4; j++)
#pragma unroll
                    for (int x = 0; x < 4; x++) s[i][j][x] = 0.f;
#pragma unroll
            for (int ks = 0; ks < 8; ks++) {
                uint32_t qf0[4], qf1[4];
                ldsm_x4(qf0[0], qf0[1], qf0[2], qf0[3], qad[0] + (uint32_t)(ks * 32));
                ldsm_x4(qf1[0], qf1[1], qf1[2], qf1[3], qad[1] + (uint32_t)(ks * 32));
#pragma unroll
                for (int jj = 0; jj < 2; jj++) {
                    int j2 = 2 * q + jj;
                    uint32_t b0, b1, b2, b3;
                    uint32_t ad = kbase +
                        (uint32_t)(((j2 * 16 + (lane & 7) + 8 * (lane >> 4)) * FST +
                                    ks * 16 + 8 * ((lane >> 3) & 1)) * 2);
                    ldsm_x4(b0, b1, b2, b3, ad);
                    mma16(s[0][2 * jj], qf0, b0, b1);
                    mma16(s[0][2 * jj + 1], qf0, b2, b3);
                    mma16(s[1][2 * jj], qf1, b0, b1);
                    mma16(s[1][2 * jj + 1], qf1, b2, b3);
                }
            }

            // PV for previous quarter overlaps the exp below via scheduler;
            // do exp first (s -> p), then PV(q-1) ordering: exp then PV keeps
            // only one p set live besides pPrev.
            uint32_t pCur[2][8];
#pragma unroll
            for (int i = 0; i < 2; i++) {
                float slo = 0.f, shi = 0.f;
#pragma unroll
                for (int j = 0; j < 4; j++) {
                    float e0 = ex2f(s[i][j][0]), e1 = ex2f(s[i][j][1]);
                    float e2 = ex2f(s[i][j][2]), e3 = ex2f(s[i][j][3]);
                    slo += e0 + e1; shi += e2 + e3;
                    pCur[i][2 * j] = h2u(__floats2half2_rn(e0, e1));
                    pCur[i][2 * j + 1] = h2u(__floats2half2_rn(e2, e3));
                }
                l_lo[i] += slo; l_hi[i] += shi;
            }

            // PV for quarter q (uses pCur; KV rows 32q..32q+31)
#pragma unroll
            for (int kk = 0; kk < 2; kk++) {
                int ks = 2 * q + kk;
#pragma unroll
                for (int jn = 0; jn < 8; jn++) {
                    uint32_t b0, b1, b2, b3;
                    uint32_t ad = vbase +
                        (uint32_t)(((ks * 16 + (lane & 15)) * FST +
                                    jn * 16 + 8 * (lane >> 4)) * 2);
                    ldsm_x4_t(b0, b1, b2, b3, ad);
                    mma16(o[0][2 * jn], &pCur[0][4 * kk], b0, b1);
                    mma16(o[0][2 * jn + 1], &pCur[0][4 * kk], b2, b3);
                    mma16(o[1][2 * jn], &pCur[1][4 * kk], b0, b1);
                    mma16(o[1][2 * jn + 1], &pCur[1][4 * kk], b2, b3);
                }
            }
            (void)pPrev;
        }
        __syncthreads();
    }

#pragma unroll
    for (int i = 0; i < 2; i++) {
        l_lo[i] += __shfl_xor_sync(0xffffffffu, l_lo[i], 1);
        l_lo[i] += __shfl_xor_sync(0xffffffffu, l_lo[i], 2);
        l_hi[i] += __shfl_xor_sync(0xffffffffu, l_hi[i], 1);
        l_hi[i] += __shfl_xor_sync(0xffffffffu, l_hi[i], 2);
    }

#pragma unroll
    for (int i = 0; i < 2; i++) {
        float inv_lo = 1.f / l_lo[i], inv_hi = 1.f / l_hi[i];
        int r = 32 * warp + 16 * i + group;
        size_t base_lo = ((size_t)(b * SEQ + q0 + r)) * D_MODEL + h * HEAD_DIM;
        size_t base_hi = base_lo + (size_t)8 * D_MODEL;
#pragma unroll
        for (int j = 0; j < 16; j++) {
            *(__half2*)&g_attn[base_lo + j * 8 + 2 * tig] =
                __floats2half2_rn(o[i][j][0] * inv_lo, o[i][j][1] * inv_lo);
            *(__half2*)&g_attn[base_hi + j * 8 + 2 * tig] =
                __floats2half2_rn(o[i][j][2] * inv_hi, o[i][j][3] * inv_hi);
        }
    }
}

// ---------------------------------------------------------------------------
extern "C" void kernel_launch(void* const* d_in, const int* in_sizes, int n_in,
                              void* d_out, int out_size) {
    const float* query = (const float*)d_in[0];
    const float* key   = (const float*)d_in[1];
    const float* value = (const float*)d_in[2];
    const float* Wq = (const float*)d_in[3];
    const float* bq = (const float*)d_in[4];
    const float* Wk = (const float*)d_in[5];
    const float* bk = (const float*)d_in[6];
    const float* Wv = (const float*)d_in[7];
    const float* bv = (const float*)d_in[8];
    const float* Wo = (const float*)d_in[9];
    const float* bo = (const float*)d_in[10];
    float* out = (float*)d_out;

    // 1) fp32 -> fp16 conversion
    dim3 gConv((MTOT * D_MODEL / 4 + 255) / 256, 7);
    conv_h<<<gConv, 256>>>(query, key, value, Wq, Wk, Wv, Wo);

    // 2) merged Q/K/V projections
    const int gemm_smem = 4 * G_STAGE * 2;   // 73728 B
    cudaFuncSetAttribute(gemm_h, cudaFuncAttributeMaxDynamicSharedMemorySize,
                         gemm_smem);
    dim3 gProj(D_MODEL / 128, MTOT / 128, 3);
    gemm_h<<<gProj, 256, gemm_smem>>>(bq, bk, bv, bo, nullptr, 0);

    // 3) flash attention (Q tile 256, 128 CTAs = one wave)
    cudaFuncSetAttribute(flash_h, cudaFuncAttributeMaxDynamicSharedMemorySize,
                         FLASH_SMEM);
    dim3 gAttn(SEQ / 256, NB * NHEAD);       // (16, 8)
    flash_h<<<gAttn, 256, FLASH_SMEM>>>();

    // 4) output projection
    dim3 gOut(D_MODEL / 128, MTOT / 128, 1);
    gemm_h<<<gOut, 256, gemm_smem>>>(bq, bk, bv, bo, out, 3);
}

// round 17
// speedup vs baseline: 1.6872x; 1.6872x over previous
#include <cuda_runtime.h>
#include <cuda_fp16.h>
#include <math.h>
#include <stdint.h>

#define D_MODEL 512
#define NHEAD 4
#define HEAD_DIM 128
#define NB 2
#define SEQ 4096
#define MTOT (NB * SEQ)
#define NT (SEQ / 128)

// fp16 scratch (allocation-free rule: device globals)
__device__ __half g_Q[NB * NHEAD * SEQ * HEAD_DIM];   // pre-scaled by scale*log2e
__device__ __half g_K[NB * NHEAD * SEQ * HEAD_DIM];
__device__ __half g_V[NB * NHEAD * SEQ * HEAD_DIM];
__device__ __half g_attn[MTOT * D_MODEL];
// fp16 copies of inputs (converted once per call)
__device__ __half g_hq[MTOT * D_MODEL];
__device__ __half g_hk[MTOT * D_MODEL];
__device__ __half g_hv[MTOT * D_MODEL];
__device__ __half g_hWq[D_MODEL * D_MODEL];
__device__ __half g_hWk[D_MODEL * D_MODEL];
__device__ __half g_hWv[D_MODEL * D_MODEL];
__device__ __half g_hWo[D_MODEL * D_MODEL];

#define Q_PRESCALE 0.1275174735772633f   // (1/sqrt(128)) * log2(e)

// ---------------------------------------------------------------------------
// helpers
// ---------------------------------------------------------------------------
__device__ __forceinline__ uint32_t smem_u32(const void* p) {
    return (uint32_t)__cvta_generic_to_shared(p);
}
__device__ __forceinline__ void ldsm_x4(uint32_t& r0, uint32_t& r1, uint32_t& r2,
                                        uint32_t& r3, uint32_t addr) {
    asm volatile("ldmatrix.sync.aligned.m8n8.x4.shared.b16 {%0,%1,%2,%3}, [%4];"
                 : "=r"(r0), "=r"(r1), "=r"(r2), "=r"(r3) : "r"(addr));
}
__device__ __forceinline__ void ldsm_x4_t(uint32_t& r0, uint32_t& r1, uint32_t& r2,
                                          uint32_t& r3, uint32_t addr) {
    asm volatile("ldmatrix.sync.aligned.m8n8.x4.trans.shared.b16 {%0,%1,%2,%3}, [%4];"
                 : "=r"(r0), "=r"(r1), "=r"(r2), "=r"(r3) : "r"(addr));
}
__device__ __forceinline__ void mma16(float* d, const uint32_t* a, uint32_t b0,
                                      uint32_t b1) {
    asm volatile(
        "mma.sync.aligned.m16n8k16.row.col.f32.f16.f16.f32 "
        "{%0,%1,%2,%3}, {%4,%5,%6,%7}, {%8,%9}, {%0,%1,%2,%3};\n"
        : "+f"(d[0]), "+f"(d[1]), "+f"(d[2]), "+f"(d[3])
        : "r"(a[0]), "r"(a[1]), "r"(a[2]), "r"(a[3]), "r"(b0), "r"(b1));
}
__device__ __forceinline__ void cp16(uint32_t dst, const void* src) {
    asm volatile("cp.async.cg.shared.global [%0], [%1], 16;" :: "r"(dst), "l"(src));
}
__device__ __forceinline__ void cp_commit() {
    asm volatile("cp.async.commit_group;");
}
__device__ __forceinline__ void cp_wait1() {
    asm volatile("cp.async.wait_group 1;");
}
__device__ __forceinline__ void cp_wait0() {
    asm volatile("cp.async.wait_group 0;");
}
__device__ __forceinline__ uint32_t h2u(__half2 v) { return *(uint32_t*)&v; }
__device__ __forceinline__ float ex2f(float x) {
    float r;
    asm("ex2.approx.f32 %0, %1;" : "=f"(r) : "f"(x));
    return r;
}

// ---------------------------------------------------------------------------
// fp32 -> fp16 conversion of inputs (once per call)
// ---------------------------------------------------------------------------
__global__ __launch_bounds__(256) void conv_h(
    const float* __restrict__ q, const float* __restrict__ k,
    const float* __restrict__ v, const float* __restrict__ wq,
    const float* __restrict__ wk, const float* __restrict__ wv,
    const float* __restrict__ wo) {
    const int z = blockIdx.y;
    const float* src;
    __half* dst;
    int n;
    switch (z) {
        case 0: src = q;  dst = g_hq;  n = MTOT * D_MODEL; break;
        case 1: src = k;  dst = g_hk;  n = MTOT * D_MODEL; break;
        case 2: src = v;  dst = g_hv;  n = MTOT * D_MODEL; break;
        case 3: src = wq; dst = g_hWq; n = D_MODEL * D_MODEL; break;
        case 4: src = wk; dst = g_hWk; n = D_MODEL * D_MODEL; break;
        case 5: src = wv; dst = g_hWv; n = D_MODEL * D_MODEL; break;
        default: src = wo; dst = g_hWo; n = D_MODEL * D_MODEL; break;
    }
    int i = (blockIdx.x * 256 + threadIdx.x) * 4;
    if (i >= n) return;
    float4 f = *(const float4*)&src[i];
    *(uint2*)&dst[i] = make_uint2(h2u(__floats2half2_rn(f.x, f.y)),
                                  h2u(__floats2half2_rn(f.z, f.w)));
}

// ---------------------------------------------------------------------------
// fp16 GEMM, cp.async double-buffered. CTA 128x128, BK=64, 8 warps (2x4).
//   mode 0: A=g_hq,  B=g_hWq -> g_Q (scaled)
//   mode 1: A=g_hk,  B=g_hWk -> g_K
//   mode 2: A=g_hWv, B=g_hv  -> g_V [B,H,S,128]
//   mode 3: A=g_attn, B=g_hWo -> fp32 Cout
// ---------------------------------------------------------------------------
#define GST 72
#define G_STAGE (128 * GST)

__global__ __launch_bounds__(256) void gemm_h(
    const float* __restrict__ bq, const float* __restrict__ bk,
    const float* __restrict__ bv, const float* __restrict__ bo,
    float* __restrict__ Cout, int base_mode) {
    extern __shared__ __align__(16) __half gsm[];

    const int mode = (base_mode == 3) ? 3 : (int)blockIdx.z;
    const __half* A = (mode == 0) ? g_hq : (mode == 1) ? g_hk
                     : (mode == 2) ? g_hWv : g_attn;
    const __half* Bm = (mode == 0) ? g_hWq : (mode == 1) ? g_hWk
                      : (mode == 2) ? g_hv : g_hWo;
    const float* bias = (mode == 0) ? bq : (mode == 1) ? bk
                       : (mode == 2) ? bv : bo;

    const int tid = threadIdx.x;
    const int lane = tid & 31, warp = tid >> 5;
    const int group = lane >> 2, tig = lane & 3;
    const int wm = warp >> 2, wn = warp & 3;
    const int m0 = (mode == 2) ? blockIdx.x * 128 : blockIdx.y * 128;
    const int n0 = (mode == 2) ? blockIdx.y * 128 : blockIdx.x * 128;

    const uint32_t smb = smem_u32(gsm);

    float acc[4][4][4];
#pragma unroll
    for (int i = 0; i < 4; i++)
#pragma unroll
        for (int j = 0; j < 4; j++)
#pragma unroll
            for (int q = 0; q < 4; q++) acc[i][j][q] = 0.f;

    auto issue_stage = [&](int it) {
        const uint32_t ab = smb + (uint32_t)((it & 1) * 2 * G_STAGE * 2);
        const uint32_t bb = ab + (uint32_t)(G_STAGE * 2);
        int k0 = it * 64;
#pragma unroll
        for (int t = 0; t < 4; t++) {
            int idx = tid + t * 256;
            int r = idx >> 3, c = (idx & 7) * 8;
            uint32_t doff = (uint32_t)((r * GST + c) * 2);
            cp16(ab + doff, A + (size_t)(m0 + r) * D_MODEL + k0 + c);
            cp16(bb + doff, Bm + (size_t)(n0 + r) * D_MODEL + k0 + c);
        }
    };

    issue_stage(0);
    cp_commit();

#pragma unroll 1
    for (int it = 0; it < 8; it++) {
        if (it < 7) {
            issue_stage(it + 1);
            cp_commit();
            cp_wait1();
        } else {
            cp_wait0();
        }
        __syncthreads();

        const uint32_t ab = smb + (uint32_t)((it & 1) * 2 * G_STAGE * 2);
        const uint32_t bb = ab + (uint32_t)(G_STAGE * 2);

#pragma unroll
        for (int ks = 0; ks < 4; ks++) {
            int kc = ks * 16;
            uint32_t a[4][4];
#pragma unroll
            for (int i = 0; i < 4; i++) {
                uint32_t ad = ab + (uint32_t)(((wm * 64 + i * 16 + (lane & 15)) * GST +
                                               kc + 8 * (lane >> 4)) * 2);
                ldsm_x4(a[i][0], a[i][1], a[i][2], a[i][3], ad);
            }
#pragma unroll
            for (int jb = 0; jb < 2; jb++) {
                int nb = wn * 32 + jb * 16;
                uint32_t b0, b1, b2, b3;
                uint32_t ad = bb + (uint32_t)(((nb + (lane & 7) + 8 * (lane >> 4)) * GST +
                                               kc + 8 * ((lane >> 3) & 1)) * 2);
                ldsm_x4(b0, b1, b2, b3, ad);
#pragma unroll
                for (int i = 0; i < 4; i++) {
                    mma16(acc[i][2 * jb], a[i], b0, b1);
                    mma16(acc[i][2 * jb + 1], a[i], b2, b3);
                }
            }
        }
        __syncthreads();
    }

#pragma unroll
    for (int i = 0; i < 4; i++) {
        int r = m0 + wm * 64 + i * 16 + group;
#pragma unroll
        for (int j = 0; j < 4; j++) {
            int c = n0 + wn * 32 + j * 8 + 2 * tig;
            if (mode == 2) {
                float v00 = acc[i][j][0] + bias[r];
                float v01 = acc[i][j][1] + bias[r];
                float v10 = acc[i][j][2] + bias[r + 8];
                float v11 = acc[i][j][3] + bias[r + 8];
                int hh = r >> 7, d = r & 127;
                int bt = c >> 12, s = c & (SEQ - 1);
                size_t p0 = (((size_t)(bt * NHEAD + hh) * SEQ) + s) * HEAD_DIM + d;
                g_V[p0] = __float2half_rn(v00);
                g_V[p0 + HEAD_DIM] = __float2half_rn(v01);
                g_V[p0 + 8] = __float2half_rn(v10);
                g_V[p0 + HEAD_DIM + 8] = __float2half_rn(v11);
            } else if (mode == 3) {
                Cout[(size_t)r * D_MODEL + c] = acc[i][j][0] + bias[c];
                Cout[(size_t)r * D_MODEL + c + 1] = acc[i][j][1] + bias[c + 1];
                Cout[(size_t)(r + 8) * D_MODEL + c] = acc[i][j][2] + bias[c];
                Cout[(size_t)(r + 8) * D_MODEL + c + 1] = acc[i][j][3] + bias[c + 1];
            } else {
                const float sc = (mode == 0) ? Q_PRESCALE : 1.0f;
                float v00 = acc[i][j][0] + bias[c];
                float v01 = acc[i][j][1] + bias[c + 1];
                float v10 = acc[i][j][2] + bias[c];
                float v11 = acc[i][j][3] + bias[c + 1];
                __half* C = (mode == 0) ? g_Q : g_K;
                int hh = c >> 7, d = c & 127;
                int b0i = r >> 12, s0 = r & (SEQ - 1);
                int b1i = (r + 8) >> 12, s1 = (r + 8) & (SEQ - 1);
                size_t p0 = (((size_t)(b0i * NHEAD + hh) * SEQ) + s0) * HEAD_DIM + d;
                size_t p1 = (((size_t)(b1i * NHEAD + hh) * SEQ) + s1) * HEAD_DIM + d;
                *(__half2*)&C[p0] = __floats2half2_rn(v00 * sc, v01 * sc);
                *(__half2*)&C[p1] = __floats2half2_rn(v10 * sc, v11 * sc);
            }
        }
    }
}

// ---------------------------------------------------------------------------
// Flash attention: Q tile 256 rows, warp owns 32 rows (2 m-blocks) so every
// K/V B-fragment feeds 4 MMAs. REGISTER-DISCIPLINED retry of R15/R16:
// quarter loop NOT unrolled (the 4x unroll replication caused the spill),
// qf reloaded per ks, everything tightly scoped. Grid (16,8) = 1 wave.
// ---------------------------------------------------------------------------
#define FST 136
#define KV_H (128 * FST)
#define Q_OFF (4 * KV_H)
#define FLASH_SMEM ((4 * KV_H + 256 * FST) * 2)   // 208896 B

__device__ __forceinline__ void issue_kv(const __half* gK, const __half* gV,
                                         uint32_t kbase, uint32_t vbase,
                                         int kt, int tid) {
#pragma unroll
    for (int t = 0; t < 8; t++) {
        int idx = tid + t * 256;
        int r = idx >> 4, c = (idx & 15) * 8;
        uint32_t doff = (uint32_t)((r * FST + c) * 2);
        size_t goff = (size_t)(kt * 128 + r) * HEAD_DIM + c;
        cp16(kbase + doff, gK + goff);
        cp16(vbase + doff, gV + goff);
    }
}

__global__ __launch_bounds__(256, 1) void flash_h() {
    extern __shared__ __align__(16) __half sh[];

    const int tid = threadIdx.x;
    const int lane = tid & 31, warp = tid >> 5;
    const int group = lane >> 2, tig = lane & 3;
    const int q0 = blockIdx.x * 256;
    const int bh = blockIdx.y;
    const int b = bh >> 2, h = bh & 3;

    const __half* gQ = g_Q + (size_t)(bh * SEQ + q0) * HEAD_DIM;
    const __half* gK = g_K + (size_t)bh * SEQ * HEAD_DIM;
    const __half* gV = g_V + (size_t)bh * SEQ * HEAD_DIM;

    uint32_t kb[2], vb[2];
    kb[0] = smem_u32(sh);
    vb[0] = smem_u32(sh + KV_H);
    kb[1] = smem_u32(sh + 2 * KV_H);
    vb[1] = smem_u32(sh + 3 * KV_H);
    const uint32_t qsb = smem_u32(sh + Q_OFF);

    issue_kv(gK, gV, kb[0], vb[0], 0, tid);
    cp_commit();

    // stage Q (256 rows)
#pragma unroll
    for (int t = 0; t < 16; t++) {
        int idx = tid + t * 256;
        int r = idx >> 4, c = (idx & 15) * 8;
        *(uint4*)&sh[Q_OFF + r * FST + c] = *(const uint4*)&gQ[(size_t)r * HEAD_DIM + c];
    }

    float o[2][16][4];
#pragma unroll
    for (int i = 0; i < 2; i++)
#pragma unroll
        for (int j = 0; j < 16; j++)
#pragma unroll
            for (int q = 0; q < 4; q++) o[i][j][q] = 0.f;
    float l_lo0 = 0.f, l_hi0 = 0.f, l_lo1 = 0.f, l_hi1 = 0.f;

    const uint32_t qad0 = qsb + (uint32_t)(((32 * warp + (lane & 15)) * FST +
                                            8 * (lane >> 4)) * 2);
    const uint32_t qad1 = qad0 + (uint32_t)(16 * FST * 2);

#pragma unroll 1
    for (int kt = 0; kt < NT; kt++) {
        if (kt + 1 < NT) {
            issue_kv(gK, gV, kb[(kt + 1) & 1], vb[(kt + 1) & 1], kt + 1, tid);
            cp_commit();
            cp_wait1();
        } else {
            cp_wait0();
        }
        __syncthreads();

        const uint32_t kbase = kb[kt & 1], vbase = vb[kt & 1];

#pragma unroll 1
        for (int q = 0; q < 4; q++) {
            // QK quarter q (S cols 32q..32q+31), both m-blocks
            float s[2][4][4];
#pragma unroll
            for (int i = 0; i < 2; i++)
#pragma unroll
                for (int j = 0; j < 4; j++)
#pragma unroll
                    for (int x = 0; x < 4; x++) s[i][j][x] = 0.f;
#pragma unroll
            for (int ks = 0; ks < 8; ks++) {
                uint32_t qf0[4], qf1[4];
                ldsm_x4(qf0[0], qf0[1], qf0[2], qf0[3], qad0 + (uint32_t)(ks * 32));
                ldsm_x4(qf1[0], qf1[1], qf1[2], qf1[3], qad1 + (uint32_t)(ks * 32));
#pragma unroll
                for (int jj = 0; jj < 2; jj++) {
                    int j2 = 2 * q + jj;
                    uint32_t b0, b1, b2, b3;
                    uint32_t ad = kbase +
                        (uint32_t)(((j2 * 16 + (lane & 7) + 8 * (lane >> 4)) * FST +
                                    ks * 16 + 8 * ((lane >> 3) & 1)) * 2);
                    ldsm_x4(b0, b1, b2, b3, ad);
                    mma16(s[0][2 * jj], qf0, b0, b1);
                    mma16(s[0][2 * jj + 1], qf0, b2, b3);
                    mma16(s[1][2 * jj], qf1, b0, b1);
                    mma16(s[1][2 * jj + 1], qf1, b2, b3);
                }
            }

            // exp -> pCur (s dies here)
            uint32_t pCur[2][8];
            {
                float a0 = 0.f, a1 = 0.f, a2 = 0.f, a3 = 0.f;
#pragma unroll
                for (int j = 0; j < 4; j++) {
                    float e0 = ex2f(s[0][j][0]), e1 = ex2f(s[0][j][1]);
                    float e2 = ex2f(s[0][j][2]), e3 = ex2f(s[0][j][3]);
                    a0 += e0 + e1; a1 += e2 + e3;
                    pCur[0][2 * j] = h2u(__floats2half2_rn(e0, e1));
                    pCur[0][2 * j + 1] = h2u(__floats2half2_rn(e2, e3));
                    float f0 = ex2f(s[1][j][0]), f1 = ex2f(s[1][j][1]);
                    float f2 = ex2f(s[1][j][2]), f3 = ex2f(s[1][j][3]);
                    a2 += f0 + f1; a3 += f2 + f3;
                    pCur[1][2 * j] = h2u(__floats2half2_rn(f0, f1));
                    pCur[1][2 * j + 1] = h2u(__floats2half2_rn(f2, f3));
                }
                l_lo0 += a0; l_hi0 += a1; l_lo1 += a2; l_hi1 += a3;
            }

            // PV for quarter q (KV rows 32q..32q+31)
#pragma unroll
            for (int kk = 0; kk < 2; kk++) {
                int ks = 2 * q + kk;
#pragma unroll
                for (int jn = 0; jn < 8; jn++) {
                    uint32_t b0, b1, b2, b3;
                    uint32_t ad = vbase +
                        (uint32_t)(((ks * 16 + (lane & 15)) * FST +
                                    jn * 16 + 8 * (lane >> 4)) * 2);
                    ldsm_x4_t(b0, b1, b2, b3, ad);
                    mma16(o[0][2 * jn], &pCur[0][4 * kk], b0, b1);
                    mma16(o[0][2 * jn + 1], &pCur[0][4 * kk], b2, b3);
                    mma16(o[1][2 * jn], &pCur[1][4 * kk], b0, b1);
                    mma16(o[1][2 * jn + 1], &pCur[1][4 * kk], b2, b3);
                }
            }
        }
        __syncthreads();
    }

    l_lo0 += __shfl_xor_sync(0xffffffffu, l_lo0, 1);
    l_lo0 += __shfl_xor_sync(0xffffffffu, l_lo0, 2);
    l_hi0 += __shfl_xor_sync(0xffffffffu, l_hi0, 1);
    l_hi0 += __shfl_xor_sync(0xffffffffu, l_hi0, 2);
    l_lo1 += __shfl_xor_sync(0xffffffffu, l_lo1, 1);
    l_lo1 += __shfl_xor_sync(0xffffffffu, l_lo1, 2);
    l_hi1 += __shfl_xor_sync(0xffffffffu, l_hi1, 1);
    l_hi1 += __shfl_xor_sync(0xffffffffu, l_hi1, 2);

#pragma unroll
    for (int i = 0; i < 2; i++) {
        float inv_lo = 1.f / (i ? l_lo1 : l_lo0);
        float inv_hi = 1.f / (i ? l_hi1 : l_hi0);
        int r = 32 * warp + 16 * i + group;
        size_t base_lo = ((size_t)(b * SEQ + q0 + r)) * D_MODEL + h * HEAD_DIM;
        size_t base_hi = base_lo + (size_t)8 * D_MODEL;
#pragma unroll
        for (int j = 0; j < 16; j++) {
            *(__half2*)&g_attn[base_lo + j * 8 + 2 * tig] =
                __floats2half2_rn(o[i][j][0] * inv_lo, o[i][j][1] * inv_lo);
            *(__half2*)&g_attn[base_hi + j * 8 + 2 * tig] =
                __floats2half2_rn(o[i][j][2] * inv_hi, o[i][j][3] * inv_hi);
        }
    }
}

// ---------------------------------------------------------------------------
extern "C" void kernel_launch(void* const* d_in, const int* in_sizes, int n_in,
                              void* d_out, int out_size) {
    const float* query = (const float*)d_in[0];
    const float* key   = (const float*)d_in[1];
    const float* value = (const float*)d_in[2];
    const float* Wq = (const float*)d_in[3];
    const float* bq = (const float*)d_in[4];
    const float* Wk = (const float*)d_in[5];
    const float* bk = (const float*)d_in[6];
    const float* Wv = (const float*)d_in[7];
    const float* bv = (const float*)d_in[8];
    const float* Wo = (const float*)d_in[9];
    const float* bo = (const float*)d_in[10];
    float* out = (float*)d_out;

    // 1) fp32 -> fp16 conversion
    dim3 gConv((MTOT * D_MODEL / 4 + 255) / 256, 7);
    conv_h<<<gConv, 256>>>(query, key, value, Wq, Wk, Wv, Wo);

    // 2) merged Q/K/V projections
    const int gemm_smem = 4 * G_STAGE * 2;   // 73728 B
    cudaFuncSetAttribute(gemm_h, cudaFuncAttributeMaxDynamicSharedMemorySize,
                         gemm_smem);
    dim3 gProj(D_MODEL / 128, MTOT / 128, 3);
    gemm_h<<<gProj, 256, gemm_smem>>>(bq, bk, bv, bo, nullptr, 0);

    // 3) flash attention (Q tile 256, 32-row warps, 1 wave)
    cudaFuncSetAttribute(flash_h, cudaFuncAttributeMaxDynamicSharedMemorySize,
                         FLASH_SMEM);
    dim3 gAttn(SEQ / 256, NB * NHEAD);       // (16, 8)
    flash_h<<<gAttn, 256, FLASH_SMEM>>>();

    // 4) output projection
    dim3 gOut(D_MODEL / 128, MTOT / 128, 1);
    gemm_h<<<gOut, 256, gemm_smem>>>(bq, bk, bv, bo, out, 3);
}